// round 7
// baseline (speedup 1.0000x reference)
#include <cuda_runtime.h>
#include <cuda_fp16.h>
#include <cstdint>

#define NB    8
#define NPTS  4096
#define KNN   8
#define DIM   128
#define TPTS  16                   // points per MLP tile (16*8 = 128 rows)
#define NTILES (NB * NPTS / TPTS)  // 2048
#define GRID_MLP 296               // 2 persistent blocks per SM

// ---------------- scratch (device globals = allowed scratch) ----------------
__device__ float g_rel[NB * NPTS * KNN * 3];                 // [point][k][3]
__device__ __align__(16) float4 g_sp[NB * NPTS];             // sorted (x,y,z,idx)
// Fragment-major fp16 weights: [layer][kt][nt][lane] -> uint2 (64 KB)
__device__ __align__(8) uint2 g_Bw[2 * 8 * 16 * 32];

// ---------------- helpers ---------------------------------------------------
__device__ __forceinline__ uint32_t packh2(float a, float b) {
    __half2 h = __floats2half2_rn(a, b);
    return *(uint32_t*)&h;
}
__device__ __forceinline__ void mma16816(float* c, const uint32_t* a,
                                         uint32_t b0, uint32_t b1) {
    asm volatile(
        "mma.sync.aligned.m16n8k16.row.col.f32.f16.f16.f32 "
        "{%0,%1,%2,%3}, {%4,%5,%6,%7}, {%8,%9}, {%0,%1,%2,%3};"
        : "+f"(c[0]), "+f"(c[1]), "+f"(c[2]), "+f"(c[3])
        : "r"(a[0]), "r"(a[1]), "r"(a[2]), "r"(a[3]), "r"(b0), "r"(b1));
}

// ---------------------------------------------------------------------------
// Per-batch bitonic sort by x. One block of 1024 threads per batch.
// Writes sorted records (x, y, z, bitcast(orig_idx)) to g_sp.
// ---------------------------------------------------------------------------
__global__ void __launch_bounds__(1024)
sort_kernel(const float* __restrict__ x) {
    __shared__ float kx[NPTS];
    __shared__ int   kid[NPTS];
    const int b   = blockIdx.x;
    const int tid = threadIdx.x;
    const float* xb = x + (size_t)b * 3 * NPTS;

    for (int i = tid; i < NPTS; i += 1024) { kx[i] = xb[i]; kid[i] = i; }
    __syncthreads();

    for (int k = 2; k <= NPTS; k <<= 1) {
        for (int j = k >> 1; j > 0; j >>= 1) {
            for (int i = tid; i < NPTS; i += 1024) {
                int ixj = i ^ j;
                if (ixj > i) {
                    bool up = ((i & k) == 0);
                    float a = kx[i], c = kx[ixj];
                    if ((a > c) == up) {
                        kx[i] = c; kx[ixj] = a;
                        int t = kid[i]; kid[i] = kid[ixj]; kid[ixj] = t;
                    }
                }
            }
            __syncthreads();
        }
    }

    float4* dst = g_sp + (size_t)b * NPTS;
    for (int i = tid; i < NPTS; i += 1024) {
        int j = kid[i];
        dst[i] = make_float4(xb[j], xb[NPTS + j], xb[2 * NPTS + j],
                             __int_as_float(j));
    }
}

// ---------------------------------------------------------------------------
// Window KNN: thread = one query (at its sorted position). Expand left/right
// in sorted-x order; stop when the nearer side's dx^2 exceeds current 8th-best
// d2 (exact: dx^2 lower-bounds d2). Selection ordered lexicographically by
// (d2, orig_idx) -> reproduces jax top_k's stable tie order exactly.
// d2 arithmetic identical to R1 (which matched with rel_err 0.0).
// ---------------------------------------------------------------------------
__global__ void __launch_bounds__(128)
knn_window(const float* __restrict__ xunused) {
    extern __shared__ float4 sp[];   // 4096 * 16B = 64 KB
    const int b   = blockIdx.y;
    const int tid = threadIdx.x;

    const float4* gsp = g_sp + (size_t)b * NPTS;
    for (int i = tid; i < NPTS; i += 128) sp[i] = gsp[i];
    __syncthreads();

    const int p = blockIdx.x * 128 + tid;    // sorted position
    const float4 qr = sp[p];
    const float qx = qr.x, qy = qr.y, qz = qr.z;
    const int   qid = __float_as_int(qr.w);
    const float sqi = fmaf(qz, qz, fmaf(qy, qy, qx * qx));

    const float FINF = 3.4e38f;
    float bd[KNN];
    int   bj[KNN];   // original indices (for stable tie order)
    int   bp[KNN];   // sorted positions (for coord gather)
#pragma unroll
    for (int s = 0; s < KNN; ++s) { bd[s] = FINF; bj[s] = 0x7fffffff; bp[s] = p; }

    int l = p - 1, r = p + 1;
    for (int it = 0; it < NPTS; ++it) {
        float dl = (l >= 0)   ? (qx - sp[l].x) : FINF;
        float dr = (r < NPTS) ? (sp[r].x - qx) : FINF;
        bool left = dl <= dr;
        float dm = left ? dl : dr;
        if (dm > 1e37f) break;                 // both sides exhausted
        if (dm * dm > bd[KNN - 1]) break;      // exact termination
        int ci = left ? l : r;
        float4 c = sp[ci];
        float sqj = fmaf(c.z, c.z, fmaf(c.y, c.y, c.x * c.x));
        float dot = fmaf(qz, c.z, fmaf(qy, c.y, qx * c.x));
        float d2  = fmaf(-2.0f, dot, sqi + sqj);
        int   cj  = __float_as_int(c.w);
        if (d2 < bd[KNN - 1] || (d2 == bd[KNN - 1] && cj < bj[KNN - 1])) {
            bd[KNN - 1] = d2; bj[KNN - 1] = cj; bp[KNN - 1] = ci;
#pragma unroll
            for (int s = KNN - 1; s > 0; --s) {
                bool sw = (bd[s] < bd[s - 1]) ||
                          (bd[s] == bd[s - 1] && bj[s] < bj[s - 1]);
                if (sw) {
                    float td = bd[s]; bd[s] = bd[s - 1]; bd[s - 1] = td;
                    int   tj = bj[s]; bj[s] = bj[s - 1]; bj[s - 1] = tj;
                    int   tp = bp[s]; bp[s] = bp[s - 1]; bp[s - 1] = tp;
                }
            }
        }
        if (left) --l; else ++r;
    }

    float rel[KNN * 3];
#pragma unroll
    for (int k = 0; k < KNN; ++k) {
        float4 c = sp[bp[k]];
        rel[k * 3 + 0] = c.x - qx;
        rel[k * 3 + 1] = c.y - qy;
        rel[k * 3 + 2] = c.z - qz;
    }
    float4* dst = (float4*)(g_rel + (size_t)(b * NPTS + qid) * (KNN * 3));
    const float4* src = (const float4*)rel;
#pragma unroll
    for (int i = 0; i < 6; ++i) dst[i] = src[i];
}

// ---------------------------------------------------------------------------
// Weight prep: fp32 -> fp16 fragment-major uint2 layout. 8192 threads.
// ---------------------------------------------------------------------------
__global__ void prep_weights(const float* __restrict__ W1,
                             const float* __restrict__ W2) {
    int i = blockIdx.x * blockDim.x + threadIdx.x;
    if (i >= 2 * 8 * 16 * 32) return;
    int lane = i & 31;
    int nt   = (i >> 5) & 15;
    int kt   = (i >> 9) & 7;
    int lay  = i >> 12;
    const float* W = lay ? W2 : W1;      // [d][c] row-major
    int n  = nt * 8 + (lane >> 2);
    int k0 = kt * 16 + (lane & 3) * 2;
    uint2 v;
    v.x = packh2(W[n * DIM + k0],     W[n * DIM + k0 + 1]);
    v.y = packh2(W[n * DIM + k0 + 8], W[n * DIM + k0 + 9]);
    g_Bw[i] = v;
}

// ---------------------------------------------------------------------------
// MLP (unchanged from R5: 83.6us, 2 blocks/SM)
// ---------------------------------------------------------------------------
__global__ void __launch_bounds__(256, 2)
mlp_kernel(const float* __restrict__ W0, float* __restrict__ out) {
    extern __shared__ __align__(8) uint2 wsm[];   // 64 KB
    __shared__ float W0s[DIM * 3];
    __shared__ float obuf[DIM * TPTS];

    const int tid  = threadIdx.x;
    const int w    = tid >> 5;
    const int lane = tid & 31;
    const int r0   = lane >> 2;
    const int q4   = lane & 3;

    for (int i = tid; i < 2 * 8 * 16 * 32; i += 256) wsm[i] = g_Bw[i];
    for (int i = tid; i < DIM * 3; i += 256) W0s[i] = W0[i];
    __syncthreads();

    uint32_t ahi[8][4];
    uint32_t nahi[8][4];

    for (int tile = blockIdx.x; tile < NTILES; tile += GRID_MLP) {
        const int pid0 = tile * TPTS;
        const int b    = pid0 >> 12;
        const int n0   = pid0 & (NPTS - 1);

        const float* ra = g_rel + (size_t)(pid0 + 2 * w)     * (KNN * 3) + r0 * 3;
        const float* rb = g_rel + (size_t)(pid0 + 2 * w + 1) * (KNN * 3) + r0 * 3;
        const float ax = ra[0], ay = ra[1], az = ra[2];
        const float bx = rb[0], by = rb[1], bz = rb[2];
#pragma unroll
        for (int kt = 0; kt < 8; ++kt) {
            const int cb = kt * 16 + q4 * 2;
            float hA[4], hB[4];
#pragma unroll
            for (int j = 0; j < 4; ++j) {
                const int c = cb + (j & 1) + (j >> 1) * 8;
                const float w0 = W0s[c * 3], w1 = W0s[c * 3 + 1], w2 = W0s[c * 3 + 2];
                hA[j] = fmaxf(fmaf(az, w2, fmaf(ay, w1, ax * w0)), 0.0f);
                hB[j] = fmaxf(fmaf(bz, w2, fmaf(by, w1, bx * w0)), 0.0f);
            }
            ahi[kt][0] = packh2(hA[0], hA[1]);
            ahi[kt][1] = packh2(hB[0], hB[1]);
            ahi[kt][2] = packh2(hA[2], hA[3]);
            ahi[kt][3] = packh2(hB[2], hB[3]);
        }

#pragma unroll
        for (int g = 0; g < 4; ++g) {
            float acc[4][4];
#pragma unroll
            for (int i = 0; i < 4; ++i)
#pragma unroll
                for (int j = 0; j < 4; ++j) acc[i][j] = 0.0f;
#pragma unroll
            for (int kt = 0; kt < 8; ++kt) {
                const uint2* bp = wsm + kt * 512 + (4 * g) * 32 + lane;
#pragma unroll
                for (int i = 0; i < 4; ++i) {
                    uint2 bw = bp[i * 32];
                    mma16816(acc[i], ahi[kt], bw.x, bw.y);
                }
            }
#pragma unroll
            for (int j = 0; j < 2; ++j) {
                nahi[2 * g + j][0] = packh2(fmaxf(acc[2 * j][0], 0.f),     fmaxf(acc[2 * j][1], 0.f));
                nahi[2 * g + j][1] = packh2(fmaxf(acc[2 * j][2], 0.f),     fmaxf(acc[2 * j][3], 0.f));
                nahi[2 * g + j][2] = packh2(fmaxf(acc[2 * j + 1][0], 0.f), fmaxf(acc[2 * j + 1][1], 0.f));
                nahi[2 * g + j][3] = packh2(fmaxf(acc[2 * j + 1][2], 0.f), fmaxf(acc[2 * j + 1][3], 0.f));
            }
        }

#pragma unroll
        for (int g = 0; g < 4; ++g) {
            float acc[4][4];
#pragma unroll
            for (int i = 0; i < 4; ++i)
#pragma unroll
                for (int j = 0; j < 4; ++j) acc[i][j] = 0.0f;
#pragma unroll
            for (int kt = 0; kt < 8; ++kt) {
                const uint2* bp = wsm + (8 + kt) * 512 + (4 * g) * 32 + lane;
#pragma unroll
                for (int i = 0; i < 4; ++i) {
                    uint2 bw = bp[i * 32];
                    mma16816(acc[i], nahi[kt], bw.x, bw.y);
                }
            }
#pragma unroll
            for (int i = 0; i < 4; ++i) {
                const int nt = 4 * g + i;
                float v0 = fmaxf(acc[i][0], 0.f), v1 = fmaxf(acc[i][1], 0.f);
                float v2 = fmaxf(acc[i][2], 0.f), v3 = fmaxf(acc[i][3], 0.f);
#pragma unroll
                for (int m = 4; m <= 16; m <<= 1) {
                    v0 = fmaxf(v0, __shfl_xor_sync(0xffffffffu, v0, m));
                    v1 = fmaxf(v1, __shfl_xor_sync(0xffffffffu, v1, m));
                    v2 = fmaxf(v2, __shfl_xor_sync(0xffffffffu, v2, m));
                    v3 = fmaxf(v3, __shfl_xor_sync(0xffffffffu, v3, m));
                }
                if (lane < 4) {
                    const int d0 = nt * 8 + q4 * 2;
                    obuf[d0 * TPTS + 2 * w]           = v0;
                    obuf[(d0 + 1) * TPTS + 2 * w]     = v1;
                    obuf[d0 * TPTS + 2 * w + 1]       = v2;
                    obuf[(d0 + 1) * TPTS + 2 * w + 1] = v3;
                }
            }
        }
        __syncthreads();

        float* ob = out + (size_t)b * DIM * NPTS + n0;
        for (int i = tid; i < DIM * TPTS; i += 256) {
            ob[(size_t)(i >> 4) * NPTS + (i & 15)] = obuf[i];
        }
        __syncthreads();
    }
}

// no-op filler: ncu captures in-call launch index 3 -> knn_window below.
__global__ void noop_kernel() {}

// ---------------------------------------------------------------------------
extern "C" void kernel_launch(void* const* d_in, const int* in_sizes, int n_in,
                              void* d_out, int out_size) {
    const float* x  = (const float*)d_in[0];
    const float* W0 = (const float*)d_in[1];
    const float* W1 = (const float*)d_in[2];
    const float* W2 = (const float*)d_in[3];
    float* out = (float*)d_out;

    const int win_smem = NPTS * (int)sizeof(float4);   // 64 KB
    const int mlp_smem = 2 * 8 * 16 * 32 * 8;          // 64 KB
    cudaFuncSetAttribute(knn_window, cudaFuncAttributeMaxDynamicSharedMemorySize, win_smem);
    cudaFuncSetAttribute(mlp_kernel, cudaFuncAttributeMaxDynamicSharedMemorySize, mlp_smem);

    sort_kernel<<<NB, 1024>>>(x);                                    // idx 0
    prep_weights<<<(2 * 8 * 16 * 32 + 255) / 256, 256>>>(W1, W2);    // idx 1
    noop_kernel<<<1, 32>>>();                                        // idx 2
    knn_window<<<dim3(NPTS / 128, NB), 128, win_smem>>>(x);          // idx 3 (ncu)
    mlp_kernel<<<GRID_MLP, 256, mlp_smem>>>(W0, out);                // idx 4
}

// round 8
// speedup vs baseline: 1.0289x; 1.0289x over previous
#include <cuda_runtime.h>
#include <cuda_fp16.h>
#include <cstdint>

#define NB    8
#define NPTS  4096
#define KNN   8
#define DIM   128
#define TPTS  16                   // points per MLP tile (16*8 = 128 rows)
#define NTILES (NB * NPTS / TPTS)  // 2048
#define GRID_MLP 296               // 2 persistent blocks per SM
#define QB    128                  // queries per KNN block
#define PAD   512                  // sorted-position pad each side
#define WMAX  (QB + 2 * PAD)       // 1152 candidate window

// ---------------- scratch (device globals = allowed scratch) ----------------
__device__ float g_rel[NB * NPTS * KNN * 3];                 // [point][k][3]
__device__ __align__(16) float4 g_sp[NB * NPTS];             // sorted (x,y,z,idx)
// Fragment-major fp16 weights: [layer][kt][nt][lane] -> uint2 (64 KB)
__device__ __align__(8) uint2 g_Bw[2 * 8 * 16 * 32];

// ---------------- helpers ---------------------------------------------------
__device__ __forceinline__ uint32_t packh2(float a, float b) {
    __half2 h = __floats2half2_rn(a, b);
    return *(uint32_t*)&h;
}
__device__ __forceinline__ void mma16816(float* c, const uint32_t* a,
                                         uint32_t b0, uint32_t b1) {
    asm volatile(
        "mma.sync.aligned.m16n8k16.row.col.f32.f16.f16.f32 "
        "{%0,%1,%2,%3}, {%4,%5,%6,%7}, {%8,%9}, {%0,%1,%2,%3};"
        : "+f"(c[0]), "+f"(c[1]), "+f"(c[2]), "+f"(c[3])
        : "r"(a[0]), "r"(a[1]), "r"(a[2]), "r"(a[3]), "r"(b0), "r"(b1));
}
// insert (d2,cj,g) into sorted-by-(d2,idx) top-8 (caller pre-tests acceptance)
__device__ __forceinline__ void ins8(float d2, int cj, int g,
                                     float* bd, int* bj, int* bg) {
    bd[KNN - 1] = d2; bj[KNN - 1] = cj; bg[KNN - 1] = g;
#pragma unroll
    for (int s = KNN - 1; s > 0; --s) {
        bool sw = (bd[s] < bd[s - 1]) ||
                  (bd[s] == bd[s - 1] && bj[s] < bj[s - 1]);
        if (sw) {
            float td = bd[s]; bd[s] = bd[s - 1]; bd[s - 1] = td;
            int   tj = bj[s]; bj[s] = bj[s - 1]; bj[s - 1] = tj;
            int   tg = bg[s]; bg[s] = bg[s - 1]; bg[s - 1] = tg;
        }
    }
}

// ---------------------------------------------------------------------------
// Per-batch bitonic sort by x (validated in R7). Writes (x,y,z,idx) to g_sp.
// ---------------------------------------------------------------------------
__global__ void __launch_bounds__(1024)
sort_kernel(const float* __restrict__ x) {
    __shared__ float kx[NPTS];
    __shared__ int   kid[NPTS];
    const int b   = blockIdx.x;
    const int tid = threadIdx.x;
    const float* xb = x + (size_t)b * 3 * NPTS;

    for (int i = tid; i < NPTS; i += 1024) { kx[i] = xb[i]; kid[i] = i; }
    __syncthreads();

    for (int k = 2; k <= NPTS; k <<= 1) {
        for (int j = k >> 1; j > 0; j >>= 1) {
            for (int i = tid; i < NPTS; i += 1024) {
                int ixj = i ^ j;
                if (ixj > i) {
                    bool up = ((i & k) == 0);
                    float a = kx[i], c = kx[ixj];
                    if ((a > c) == up) {
                        kx[i] = c; kx[ixj] = a;
                        int t = kid[i]; kid[i] = kid[ixj]; kid[ixj] = t;
                    }
                }
            }
            __syncthreads();
        }
    }

    float4* dst = g_sp + (size_t)b * NPTS;
    for (int i = tid; i < NPTS; i += 1024) {
        int j = kid[i];
        dst[i] = make_float4(xb[j], xb[NPTS + j], xb[2 * NPTS + j],
                             __int_as_float(j));
    }
}

// ---------------------------------------------------------------------------
// Windowed dense KNN: block = 128 consecutive sorted queries; 256 threads.
// Threads t and t+128 both own query t and scan even/odd window candidates
// (candidate index uniform across the warp -> broadcast LDS, R6-style).
// After merge, coverage check vs first point outside the window; exact
// fallback walk (rare). Selection by lexicographic (d2, orig_idx).
// ---------------------------------------------------------------------------
__global__ void __launch_bounds__(256)
knn_scan(const float* __restrict__ xunused) {
    __shared__ __align__(16) float4 cpt[WMAX];
    __shared__ float csq[WMAX];
    __shared__ float dm_d[KNN][QB];
    __shared__ int   dm_i[KNN][QB];
    __shared__ int   dm_g[KNN][QB];

    const int b   = blockIdx.y;
    const int Q0  = blockIdx.x * QB;
    const int tid = threadIdx.x;
    const float4* gsp = g_sp + (size_t)b * NPTS;

    const int winstart = max(0, Q0 - PAD);
    const int winend   = min(NPTS, Q0 + QB + PAD);
    const int count    = winend - winstart;

    for (int i = tid; i < count; i += 256) {
        float4 c = gsp[winstart + i];
        cpt[i] = c;
        csq[i] = c.x * c.x + c.y * c.y + c.z * c.z;
    }
    __syncthreads();

    const int qt     = tid & (QB - 1);
    const int parity = tid >> 7;                // 0 or 1
    const int p      = Q0 + qt;                 // my query's sorted position
    const float4 qr  = cpt[p - winstart];
    const float qx = qr.x, qy = qr.y, qz = qr.z;
    const int   qid = __float_as_int(qr.w);
    const float sqi = qx * qx + qy * qy + qz * qz;
    const float FINF = 3.4e38f;

    float bd[KNN]; int bj[KNN]; int bg[KNN];
#pragma unroll
    for (int s = 0; s < KNN; ++s) { bd[s] = FINF; bj[s] = 0x7fffffff; bg[s] = 0; }

    for (int i = parity; i < count; i += 2) {
        float4 c = cpt[i];
        float dot = fmaf(qz, c.z, fmaf(qy, c.y, qx * c.x));
        float d2  = fmaf(-2.0f, dot, sqi + csq[i]);
        int   cj  = __float_as_int(c.w);
        if ((d2 < bd[KNN - 1] ||
             (d2 == bd[KNN - 1] && cj < bj[KNN - 1])) && cj != qid)
            ins8(d2, cj, winstart + i, bd, bj, bg);
    }

    if (parity == 1) {
#pragma unroll
        for (int k = 0; k < KNN; ++k) {
            dm_d[k][qt] = bd[k]; dm_i[k][qt] = bj[k]; dm_g[k][qt] = bg[k];
        }
    }
    __syncthreads();
    if (parity == 0) {
        // merge partner's top-8
#pragma unroll
        for (int k = 0; k < KNN; ++k) {
            float d2 = dm_d[k][qt]; int cj = dm_i[k][qt]; int g = dm_g[k][qt];
            if (d2 < bd[KNN - 1] ||
                (d2 == bd[KNN - 1] && cj < bj[KNN - 1]))
                ins8(d2, cj, g, bd, bj, bg);
        }

        // exact coverage fallback (x sorted: farther => larger dx^2)
        int l = winstart - 1;
        while (l >= 0) {
            float4 c = gsp[l];
            float dx = qx - c.x;
            if (dx * dx > bd[KNN - 1]) break;
            float sqj = c.x * c.x + c.y * c.y + c.z * c.z;
            float dot = fmaf(qz, c.z, fmaf(qy, c.y, qx * c.x));
            float d2  = fmaf(-2.0f, dot, sqi + sqj);
            int   cj  = __float_as_int(c.w);
            if ((d2 < bd[KNN - 1] ||
                 (d2 == bd[KNN - 1] && cj < bj[KNN - 1])) && cj != qid)
                ins8(d2, cj, l, bd, bj, bg);
            --l;
        }
        int r = winend;
        while (r < NPTS) {
            float4 c = gsp[r];
            float dx = c.x - qx;
            if (dx * dx > bd[KNN - 1]) break;
            float sqj = c.x * c.x + c.y * c.y + c.z * c.z;
            float dot = fmaf(qz, c.z, fmaf(qy, c.y, qx * c.x));
            float d2  = fmaf(-2.0f, dot, sqi + sqj);
            int   cj  = __float_as_int(c.w);
            if ((d2 < bd[KNN - 1] ||
                 (d2 == bd[KNN - 1] && cj < bj[KNN - 1])) && cj != qid)
                ins8(d2, cj, r, bd, bj, bg);
            ++r;
        }

        // gather rel = nbr - self, write by ORIGINAL point id
        float rel[KNN * 3];
#pragma unroll
        for (int k = 0; k < KNN; ++k) {
            float4 c = gsp[bg[k]];
            rel[k * 3 + 0] = c.x - qx;
            rel[k * 3 + 1] = c.y - qy;
            rel[k * 3 + 2] = c.z - qz;
        }
        float4* dst = (float4*)(g_rel + (size_t)(b * NPTS + qid) * (KNN * 3));
        const float4* src = (const float4*)rel;
#pragma unroll
        for (int i = 0; i < 6; ++i) dst[i] = src[i];
    }
}

// ---------------------------------------------------------------------------
// Weight prep: fp32 -> fp16 fragment-major uint2 layout. 8192 threads.
// ---------------------------------------------------------------------------
__global__ void prep_weights(const float* __restrict__ W1,
                             const float* __restrict__ W2) {
    int i = blockIdx.x * blockDim.x + threadIdx.x;
    if (i >= 2 * 8 * 16 * 32) return;
    int lane = i & 31;
    int nt   = (i >> 5) & 15;
    int kt   = (i >> 9) & 7;
    int lay  = i >> 12;
    const float* W = lay ? W2 : W1;      // [d][c] row-major
    int n  = nt * 8 + (lane >> 2);
    int k0 = kt * 16 + (lane & 3) * 2;
    uint2 v;
    v.x = packh2(W[n * DIM + k0],     W[n * DIM + k0 + 1]);
    v.y = packh2(W[n * DIM + k0 + 8], W[n * DIM + k0 + 9]);
    g_Bw[i] = v;
}

// ---------------------------------------------------------------------------
// MLP (unchanged from R5: 83.6us, 2 blocks/SM)
// ---------------------------------------------------------------------------
__global__ void __launch_bounds__(256, 2)
mlp_kernel(const float* __restrict__ W0, float* __restrict__ out) {
    extern __shared__ __align__(8) uint2 wsm[];   // 64 KB
    __shared__ float W0s[DIM * 3];
    __shared__ float obuf[DIM * TPTS];

    const int tid  = threadIdx.x;
    const int w    = tid >> 5;
    const int lane = tid & 31;
    const int r0   = lane >> 2;
    const int q4   = lane & 3;

    for (int i = tid; i < 2 * 8 * 16 * 32; i += 256) wsm[i] = g_Bw[i];
    for (int i = tid; i < DIM * 3; i += 256) W0s[i] = W0[i];
    __syncthreads();

    uint32_t ahi[8][4];
    uint32_t nahi[8][4];

    for (int tile = blockIdx.x; tile < NTILES; tile += GRID_MLP) {
        const int pid0 = tile * TPTS;
        const int b    = pid0 >> 12;
        const int n0   = pid0 & (NPTS - 1);

        const float* ra = g_rel + (size_t)(pid0 + 2 * w)     * (KNN * 3) + r0 * 3;
        const float* rb = g_rel + (size_t)(pid0 + 2 * w + 1) * (KNN * 3) + r0 * 3;
        const float ax = ra[0], ay = ra[1], az = ra[2];
        const float bx = rb[0], by = rb[1], bz = rb[2];
#pragma unroll
        for (int kt = 0; kt < 8; ++kt) {
            const int cb = kt * 16 + q4 * 2;
            float hA[4], hB[4];
#pragma unroll
            for (int j = 0; j < 4; ++j) {
                const int c = cb + (j & 1) + (j >> 1) * 8;
                const float w0 = W0s[c * 3], w1 = W0s[c * 3 + 1], w2 = W0s[c * 3 + 2];
                hA[j] = fmaxf(fmaf(az, w2, fmaf(ay, w1, ax * w0)), 0.0f);
                hB[j] = fmaxf(fmaf(bz, w2, fmaf(by, w1, bx * w0)), 0.0f);
            }
            ahi[kt][0] = packh2(hA[0], hA[1]);
            ahi[kt][1] = packh2(hB[0], hB[1]);
            ahi[kt][2] = packh2(hA[2], hA[3]);
            ahi[kt][3] = packh2(hB[2], hB[3]);
        }

#pragma unroll
        for (int g = 0; g < 4; ++g) {
            float acc[4][4];
#pragma unroll
            for (int i = 0; i < 4; ++i)
#pragma unroll
                for (int j = 0; j < 4; ++j) acc[i][j] = 0.0f;
#pragma unroll
            for (int kt = 0; kt < 8; ++kt) {
                const uint2* bp = wsm + kt * 512 + (4 * g) * 32 + lane;
#pragma unroll
                for (int i = 0; i < 4; ++i) {
                    uint2 bw = bp[i * 32];
                    mma16816(acc[i], ahi[kt], bw.x, bw.y);
                }
            }
#pragma unroll
            for (int j = 0; j < 2; ++j) {
                nahi[2 * g + j][0] = packh2(fmaxf(acc[2 * j][0], 0.f),     fmaxf(acc[2 * j][1], 0.f));
                nahi[2 * g + j][1] = packh2(fmaxf(acc[2 * j][2], 0.f),     fmaxf(acc[2 * j][3], 0.f));
                nahi[2 * g + j][2] = packh2(fmaxf(acc[2 * j + 1][0], 0.f), fmaxf(acc[2 * j + 1][1], 0.f));
                nahi[2 * g + j][3] = packh2(fmaxf(acc[2 * j + 1][2], 0.f), fmaxf(acc[2 * j + 1][3], 0.f));
            }
        }

#pragma unroll
        for (int g = 0; g < 4; ++g) {
            float acc[4][4];
#pragma unroll
            for (int i = 0; i < 4; ++i)
#pragma unroll
                for (int j = 0; j < 4; ++j) acc[i][j] = 0.0f;
#pragma unroll
            for (int kt = 0; kt < 8; ++kt) {
                const uint2* bp = wsm + (8 + kt) * 512 + (4 * g) * 32 + lane;
#pragma unroll
                for (int i = 0; i < 4; ++i) {
                    uint2 bw = bp[i * 32];
                    mma16816(acc[i], nahi[kt], bw.x, bw.y);
                }
            }
#pragma unroll
            for (int i = 0; i < 4; ++i) {
                const int nt = 4 * g + i;
                float v0 = fmaxf(acc[i][0], 0.f), v1 = fmaxf(acc[i][1], 0.f);
                float v2 = fmaxf(acc[i][2], 0.f), v3 = fmaxf(acc[i][3], 0.f);
#pragma unroll
                for (int m = 4; m <= 16; m <<= 1) {
                    v0 = fmaxf(v0, __shfl_xor_sync(0xffffffffu, v0, m));
                    v1 = fmaxf(v1, __shfl_xor_sync(0xffffffffu, v1, m));
                    v2 = fmaxf(v2, __shfl_xor_sync(0xffffffffu, v2, m));
                    v3 = fmaxf(v3, __shfl_xor_sync(0xffffffffu, v3, m));
                }
                if (lane < 4) {
                    const int d0 = nt * 8 + q4 * 2;
                    obuf[d0 * TPTS + 2 * w]           = v0;
                    obuf[(d0 + 1) * TPTS + 2 * w]     = v1;
                    obuf[d0 * TPTS + 2 * w + 1]       = v2;
                    obuf[(d0 + 1) * TPTS + 2 * w + 1] = v3;
                }
            }
        }
        __syncthreads();

        float* ob = out + (size_t)b * DIM * NPTS + n0;
        for (int i = tid; i < DIM * TPTS; i += 256) {
            ob[(size_t)(i >> 4) * NPTS + (i & 15)] = obuf[i];
        }
        __syncthreads();
    }
}

// no-op filler: ncu captures in-call launch index 3 -> knn_scan below.
__global__ void noop_kernel() {}

// ---------------------------------------------------------------------------
extern "C" void kernel_launch(void* const* d_in, const int* in_sizes, int n_in,
                              void* d_out, int out_size) {
    const float* x  = (const float*)d_in[0];
    const float* W0 = (const float*)d_in[1];
    const float* W1 = (const float*)d_in[2];
    const float* W2 = (const float*)d_in[3];
    float* out = (float*)d_out;

    const int mlp_smem = 2 * 8 * 16 * 32 * 8;          // 64 KB
    cudaFuncSetAttribute(mlp_kernel, cudaFuncAttributeMaxDynamicSharedMemorySize, mlp_smem);

    sort_kernel<<<NB, 1024>>>(x);                                    // idx 0
    prep_weights<<<(2 * 8 * 16 * 32 + 255) / 256, 256>>>(W1, W2);    // idx 1
    noop_kernel<<<1, 32>>>();                                        // idx 2
    knn_scan<<<dim3(NPTS / QB, NB), 256>>>(x);                       // idx 3 (ncu)
    mlp_kernel<<<GRID_MLP, 256, mlp_smem>>>(W0, out);                // idx 4
}

// round 9
// speedup vs baseline: 1.2408x; 1.2059x over previous
#include <cuda_runtime.h>
#include <cuda_fp16.h>
#include <cstdint>

#define NB    8
#define NPTS  4096
#define KNN   8
#define DIM   128
#define TPTS  16                   // points per MLP tile (16*8 = 128 rows)
#define NTILES (NB * NPTS / TPTS)  // 2048
#define GRID_MLP 296               // 2 persistent blocks per SM
#define QB    128                  // queries per KNN block
#define PAD   512                  // sorted-position pad each side
#define WMAX  (QB + 2 * PAD)       // 1152 candidate window
#define NPAR  4                    // scanner threads per query

// ---------------- scratch (device globals = allowed scratch) ----------------
__device__ float g_rel[NB * NPTS * KNN * 3];                 // [point][k][3]
__device__ __align__(16) float4 g_sp[NB * NPTS];             // sorted (x,y,z,idx)
// Fragment-major fp16 weights: [layer][kt][nt][lane] -> uint2 (64 KB)
__device__ __align__(8) uint2 g_Bw[2 * 8 * 16 * 32];

// ---------------- helpers ---------------------------------------------------
__device__ __forceinline__ uint32_t packh2(float a, float b) {
    __half2 h = __floats2half2_rn(a, b);
    return *(uint32_t*)&h;
}
__device__ __forceinline__ void mma16816(float* c, const uint32_t* a,
                                         uint32_t b0, uint32_t b1) {
    asm volatile(
        "mma.sync.aligned.m16n8k16.row.col.f32.f16.f16.f32 "
        "{%0,%1,%2,%3}, {%4,%5,%6,%7}, {%8,%9}, {%0,%1,%2,%3};"
        : "+f"(c[0]), "+f"(c[1]), "+f"(c[2]), "+f"(c[3])
        : "r"(a[0]), "r"(a[1]), "r"(a[2]), "r"(a[3]), "r"(b0), "r"(b1));
}
// lean insert: caller pre-tested d2 < bd[7]; g = global sorted position
__device__ __forceinline__ void ins8(float d2, int g, float* bd, int* bg) {
    bd[KNN - 1] = d2; bg[KNN - 1] = g;
#pragma unroll
    for (int s = KNN - 1; s > 0; --s) {
        if (bd[s] < bd[s - 1]) {
            float td = bd[s]; bd[s] = bd[s - 1]; bd[s - 1] = td;
            int   tg = bg[s]; bg[s] = bg[s - 1]; bg[s - 1] = tg;
        }
    }
}

// ---------------------------------------------------------------------------
// Per-batch bitonic sort by x. Writes (x,y,z,idx) to g_sp.
// ---------------------------------------------------------------------------
__global__ void __launch_bounds__(1024)
sort_kernel(const float* __restrict__ x) {
    __shared__ float kx[NPTS];
    __shared__ int   kid[NPTS];
    const int b   = blockIdx.x;
    const int tid = threadIdx.x;
    const float* xb = x + (size_t)b * 3 * NPTS;

    for (int i = tid; i < NPTS; i += 1024) { kx[i] = xb[i]; kid[i] = i; }
    __syncthreads();

    for (int k = 2; k <= NPTS; k <<= 1) {
        for (int j = k >> 1; j > 0; j >>= 1) {
            for (int i = tid; i < NPTS; i += 1024) {
                int ixj = i ^ j;
                if (ixj > i) {
                    bool up = ((i & k) == 0);
                    float a = kx[i], c = kx[ixj];
                    if ((a > c) == up) {
                        kx[i] = c; kx[ixj] = a;
                        int t = kid[i]; kid[i] = kid[ixj]; kid[ixj] = t;
                    }
                }
            }
            __syncthreads();
        }
    }

    float4* dst = g_sp + (size_t)b * NPTS;
    for (int i = tid; i < NPTS; i += 1024) {
        int j = kid[i];
        dst[i] = make_float4(xb[j], xb[NPTS + j], xb[2 * NPTS + j],
                             __int_as_float(j));
    }
}

// ---------------------------------------------------------------------------
// Windowed dense KNN, center-out scan. Block = 128 consecutive sorted
// queries, 512 threads = 4 scanners/query (stride-4 over the center-out
// candidate sequence). Top-8 saturates within the first few dozen
// candidates -> insert body almost never runs afterwards. Exactness via the
// post-merge coverage walk outside the window (dx^2 lower-bounds d2).
// ---------------------------------------------------------------------------
__global__ void __launch_bounds__(512)
knn_scan(const float* __restrict__ xunused) {
    __shared__ __align__(16) float4 cpt[WMAX];
    __shared__ float csq[WMAX];
    __shared__ float pdm[NPAR - 1][KNN][QB];
    __shared__ int   pgm[NPAR - 1][KNN][QB];

    const int b   = blockIdx.y;
    const int Q0  = blockIdx.x * QB;
    const int tid = threadIdx.x;
    const float4* gsp = g_sp + (size_t)b * NPTS;

    const int winstart = max(0, Q0 - PAD);
    const int winend   = min(NPTS, Q0 + QB + PAD);
    const int count    = winend - winstart;    // always even (QB, PAD even)
    const int wc       = count >> 1;

    for (int i = tid; i < count; i += 512) {
        float4 c = gsp[winstart + i];
        cpt[i] = c;
        csq[i] = c.x * c.x + c.y * c.y + c.z * c.z;
    }
    __syncthreads();

    const int qt  = tid & (QB - 1);
    const int par = tid >> 7;                  // 0..3
    const int p   = Q0 + qt;
    const int qloc = p - winstart;
    const float4 qr = cpt[qloc];
    const float qx = qr.x, qy = qr.y, qz = qr.z;
    const int   qid = __float_as_int(qr.w);
    const float sqi = qx * qx + qy * qy + qz * qz;
    const float FINF = 3.4e38f;

    float bd[KNN]; int bg[KNN];
#pragma unroll
    for (int s = 0; s < KNN; ++s) { bd[s] = FINF; bg[s] = winstart + qloc; }

    // center-out: j -> o covers [0,count) from the middle outwards
    for (int j = par; j < count; j += NPAR) {
        int h = j >> 1;
        int o = (j & 1) ? (wc - 1 - h) : (wc + h);
        float4 c = cpt[o];
        float dot = fmaf(qz, c.z, fmaf(qy, c.y, qx * c.x));
        float d2  = fmaf(-2.0f, dot, sqi + csq[o]);
        if (d2 < bd[KNN - 1] && o != qloc)
            ins8(d2, winstart + o, bd, bg);
    }

    if (par > 0) {
#pragma unroll
        for (int k = 0; k < KNN; ++k) {
            pdm[par - 1][k][qt] = bd[k];
            pgm[par - 1][k][qt] = bg[k];
        }
    }
    __syncthreads();
    if (par == 0) {
#pragma unroll
        for (int m = 0; m < NPAR - 1; ++m)
#pragma unroll
            for (int k = 0; k < KNN; ++k) {
                float d2 = pdm[m][k][qt];
                if (d2 < bd[KNN - 1]) ins8(d2, pgm[m][k][qt], bd, bg);
            }

        // exact coverage fallback outside the window (rare)
        int l = winstart - 1;
        while (l >= 0) {
            float4 c = gsp[l];
            float dx = qx - c.x;
            if (dx * dx > bd[KNN - 1]) break;
            float sqj = c.x * c.x + c.y * c.y + c.z * c.z;
            float dot = fmaf(qz, c.z, fmaf(qy, c.y, qx * c.x));
            float d2  = fmaf(-2.0f, dot, sqi + sqj);
            if (d2 < bd[KNN - 1]) ins8(d2, l, bd, bg);
            --l;
        }
        int r = winend;
        while (r < NPTS) {
            float4 c = gsp[r];
            float dx = c.x - qx;
            if (dx * dx > bd[KNN - 1]) break;
            float sqj = c.x * c.x + c.y * c.y + c.z * c.z;
            float dot = fmaf(qz, c.z, fmaf(qy, c.y, qx * c.x));
            float d2  = fmaf(-2.0f, dot, sqi + sqj);
            if (d2 < bd[KNN - 1]) ins8(d2, r, bd, bg);
            ++r;
        }

        float rel[KNN * 3];
#pragma unroll
        for (int k = 0; k < KNN; ++k) {
            float4 c = gsp[bg[k]];
            rel[k * 3 + 0] = c.x - qx;
            rel[k * 3 + 1] = c.y - qy;
            rel[k * 3 + 2] = c.z - qz;
        }
        float4* dst = (float4*)(g_rel + (size_t)(b * NPTS + qid) * (KNN * 3));
        const float4* src = (const float4*)rel;
#pragma unroll
        for (int i = 0; i < 6; ++i) dst[i] = src[i];
    }
}

// ---------------------------------------------------------------------------
// Weight prep: fp32 -> fp16 fragment-major uint2 layout. 8192 threads.
// ---------------------------------------------------------------------------
__global__ void prep_weights(const float* __restrict__ W1,
                             const float* __restrict__ W2) {
    int i = blockIdx.x * blockDim.x + threadIdx.x;
    if (i >= 2 * 8 * 16 * 32) return;
    int lane = i & 31;
    int nt   = (i >> 5) & 15;
    int kt   = (i >> 9) & 7;
    int lay  = i >> 12;
    const float* W = lay ? W2 : W1;      // [d][c] row-major
    int n  = nt * 8 + (lane >> 2);
    int k0 = kt * 16 + (lane & 3) * 2;
    uint2 v;
    v.x = packh2(W[n * DIM + k0],     W[n * DIM + k0 + 1]);
    v.y = packh2(W[n * DIM + k0 + 8], W[n * DIM + k0 + 9]);
    g_Bw[i] = v;
}

// ---------------------------------------------------------------------------
// MLP (unchanged from R5: 83.6us, 2 blocks/SM)
// ---------------------------------------------------------------------------
__global__ void __launch_bounds__(256, 2)
mlp_kernel(const float* __restrict__ W0, float* __restrict__ out) {
    extern __shared__ __align__(8) uint2 wsm[];   // 64 KB
    __shared__ float W0s[DIM * 3];
    __shared__ float obuf[DIM * TPTS];

    const int tid  = threadIdx.x;
    const int w    = tid >> 5;
    const int lane = tid & 31;
    const int r0   = lane >> 2;
    const int q4   = lane & 3;

    for (int i = tid; i < 2 * 8 * 16 * 32; i += 256) wsm[i] = g_Bw[i];
    for (int i = tid; i < DIM * 3; i += 256) W0s[i] = W0[i];
    __syncthreads();

    uint32_t ahi[8][4];
    uint32_t nahi[8][4];

    for (int tile = blockIdx.x; tile < NTILES; tile += GRID_MLP) {
        const int pid0 = tile * TPTS;
        const int b    = pid0 >> 12;
        const int n0   = pid0 & (NPTS - 1);

        const float* ra = g_rel + (size_t)(pid0 + 2 * w)     * (KNN * 3) + r0 * 3;
        const float* rb = g_rel + (size_t)(pid0 + 2 * w + 1) * (KNN * 3) + r0 * 3;
        const float ax = ra[0], ay = ra[1], az = ra[2];
        const float bx = rb[0], by = rb[1], bz = rb[2];
#pragma unroll
        for (int kt = 0; kt < 8; ++kt) {
            const int cb = kt * 16 + q4 * 2;
            float hA[4], hB[4];
#pragma unroll
            for (int j = 0; j < 4; ++j) {
                const int c = cb + (j & 1) + (j >> 1) * 8;
                const float w0 = W0s[c * 3], w1 = W0s[c * 3 + 1], w2 = W0s[c * 3 + 2];
                hA[j] = fmaxf(fmaf(az, w2, fmaf(ay, w1, ax * w0)), 0.0f);
                hB[j] = fmaxf(fmaf(bz, w2, fmaf(by, w1, bx * w0)), 0.0f);
            }
            ahi[kt][0] = packh2(hA[0], hA[1]);
            ahi[kt][1] = packh2(hB[0], hB[1]);
            ahi[kt][2] = packh2(hA[2], hA[3]);
            ahi[kt][3] = packh2(hB[2], hB[3]);
        }

#pragma unroll
        for (int g = 0; g < 4; ++g) {
            float acc[4][4];
#pragma unroll
            for (int i = 0; i < 4; ++i)
#pragma unroll
                for (int j = 0; j < 4; ++j) acc[i][j] = 0.0f;
#pragma unroll
            for (int kt = 0; kt < 8; ++kt) {
                const uint2* bp = wsm + kt * 512 + (4 * g) * 32 + lane;
#pragma unroll
                for (int i = 0; i < 4; ++i) {
                    uint2 bw = bp[i * 32];
                    mma16816(acc[i], ahi[kt], bw.x, bw.y);
                }
            }
#pragma unroll
            for (int j = 0; j < 2; ++j) {
                nahi[2 * g + j][0] = packh2(fmaxf(acc[2 * j][0], 0.f),     fmaxf(acc[2 * j][1], 0.f));
                nahi[2 * g + j][1] = packh2(fmaxf(acc[2 * j][2], 0.f),     fmaxf(acc[2 * j][3], 0.f));
                nahi[2 * g + j][2] = packh2(fmaxf(acc[2 * j + 1][0], 0.f), fmaxf(acc[2 * j + 1][1], 0.f));
                nahi[2 * g + j][3] = packh2(fmaxf(acc[2 * j + 1][2], 0.f), fmaxf(acc[2 * j + 1][3], 0.f));
            }
        }

#pragma unroll
        for (int g = 0; g < 4; ++g) {
            float acc[4][4];
#pragma unroll
            for (int i = 0; i < 4; ++i)
#pragma unroll
                for (int j = 0; j < 4; ++j) acc[i][j] = 0.0f;
#pragma unroll
            for (int kt = 0; kt < 8; ++kt) {
                const uint2* bp = wsm + (8 + kt) * 512 + (4 * g) * 32 + lane;
#pragma unroll
                for (int i = 0; i < 4; ++i) {
                    uint2 bw = bp[i * 32];
                    mma16816(acc[i], nahi[kt], bw.x, bw.y);
                }
            }
#pragma unroll
            for (int i = 0; i < 4; ++i) {
                const int nt = 4 * g + i;
                float v0 = fmaxf(acc[i][0], 0.f), v1 = fmaxf(acc[i][1], 0.f);
                float v2 = fmaxf(acc[i][2], 0.f), v3 = fmaxf(acc[i][3], 0.f);
#pragma unroll
                for (int m = 4; m <= 16; m <<= 1) {
                    v0 = fmaxf(v0, __shfl_xor_sync(0xffffffffu, v0, m));
                    v1 = fmaxf(v1, __shfl_xor_sync(0xffffffffu, v1, m));
                    v2 = fmaxf(v2, __shfl_xor_sync(0xffffffffu, v2, m));
                    v3 = fmaxf(v3, __shfl_xor_sync(0xffffffffu, v3, m));
                }
                if (lane < 4) {
                    const int d0 = nt * 8 + q4 * 2;
                    obuf[d0 * TPTS + 2 * w]           = v0;
                    obuf[(d0 + 1) * TPTS + 2 * w]     = v1;
                    obuf[d0 * TPTS + 2 * w + 1]       = v2;
                    obuf[(d0 + 1) * TPTS + 2 * w + 1] = v3;
                }
            }
        }
        __syncthreads();

        float* ob = out + (size_t)b * DIM * NPTS + n0;
        for (int i = tid; i < DIM * TPTS; i += 256) {
            ob[(size_t)(i >> 4) * NPTS + (i & 15)] = obuf[i];
        }
        __syncthreads();
    }
}

// no-op filler: ncu captures in-call launch index 3 -> knn_scan below.
__global__ void noop_kernel() {}

// ---------------------------------------------------------------------------
extern "C" void kernel_launch(void* const* d_in, const int* in_sizes, int n_in,
                              void* d_out, int out_size) {
    const float* x  = (const float*)d_in[0];
    const float* W0 = (const float*)d_in[1];
    const float* W1 = (const float*)d_in[2];
    const float* W2 = (const float*)d_in[3];
    float* out = (float*)d_out;

    const int mlp_smem = 2 * 8 * 16 * 32 * 8;          // 64 KB
    cudaFuncSetAttribute(mlp_kernel, cudaFuncAttributeMaxDynamicSharedMemorySize, mlp_smem);

    sort_kernel<<<NB, 1024>>>(x);                                    // idx 0
    prep_weights<<<(2 * 8 * 16 * 32 + 255) / 256, 256>>>(W1, W2);    // idx 1
    noop_kernel<<<1, 32>>>();                                        // idx 2
    knn_scan<<<dim3(NPTS / QB, NB), 512>>>(x);                       // idx 3 (ncu)
    mlp_kernel<<<GRID_MLP, 256, mlp_smem>>>(W0, out);                // idx 4
}